// round 14
// baseline (speedup 1.0000x reference)
#include <cuda_runtime.h>
#include <cuda_fp16.h>
#include <cstdint>

#define BS   8192
#define DIM  4096
#define BLK  64
#define NB   64
#define HID  128

// ================= device scratch (no allocs allowed) =================
__device__ float g_bufA[(size_t)BS * DIM];
__device__ float g_bufB[(size_t)BS * DIM];
// prepped fp16 weights, dense k-contiguous:
//   W1^T: [t][e=128][d=64]   W2^T: [t][o=64][e=128]     (t = layer*64 + n)
__device__ __half g_w1t[2 * 64 * 8192];
__device__ __half g_w2t[2 * 64 * 8192];

// ================= smem layout (bytes) =================
// Phase 1 (GEMM1):  A fp16 [0,18432)  W1 fp16 [18432,36864)
// Phase 2 (GEMM2):  H fp16 [0,34816)   (overlays A+W1)
// Phase 3 (store):  OUT f32 [0,34816)  (overlays H)
// Always:           W2 fp16 [36864,54272)  b1/b2 [54272,55040)
#define SB_A      0
#define SB_W1     18432
#define SB_H      0
#define SB_OUT    0
#define SB_W2     36864
#define SB_B1     54272
#define SB_B2     54784
#define SMEM_TOTAL 55040

#define LDA 72    // fp16 stride, A / W1^T  (144 B/row: LDSM conflict-free)
#define LDH 136   // fp16 stride, H / W2^T  (272 B/row: LDSM conflict-free)

__device__ __forceinline__ uint32_t smem_u32(const void* p) {
    uint32_t a;
    asm("{ .reg .u64 t; cvta.to.shared.u64 t, %1; cvt.u32.u64 %0, t; }" : "=r"(a) : "l"(p));
    return a;
}

__device__ __forceinline__ uint32_t pack_h2(float a, float b) {
    __half2 h = __floats2half2_rn(a, b);
    return *reinterpret_cast<uint32_t*>(&h);
}

// D = A(16x16,row) * B(16x8,col) + D ; fp16 in, f32 accum
__device__ __forceinline__ void mma16816(float* c, uint32_t a0, uint32_t a1,
                                         uint32_t a2, uint32_t a3,
                                         uint32_t b0, uint32_t b1) {
    asm("mma.sync.aligned.m16n8k16.row.col.f32.f16.f16.f32 "
        "{%0,%1,%2,%3}, {%4,%5,%6,%7}, {%8,%9}, {%0,%1,%2,%3};"
        : "+f"(c[0]), "+f"(c[1]), "+f"(c[2]), "+f"(c[3])
        : "r"(a0), "r"(a1), "r"(a2), "r"(a3), "r"(b0), "r"(b1));
}

__device__ __forceinline__ void ldsm4(uint32_t& r0, uint32_t& r1, uint32_t& r2,
                                      uint32_t& r3, uint32_t addr) {
    asm volatile("ldmatrix.sync.aligned.m8n8.x4.shared.b16 {%0,%1,%2,%3}, [%4];"
                 : "=r"(r0), "=r"(r1), "=r"(r2), "=r"(r3) : "r"(addr));
}

__device__ __forceinline__ float elu1(float v) {
    return (v > 0.f) ? v : (__expf(v) - 1.f);
}

// ============== weight prep: fp32 -> transposed fp16 ==============
__global__ void prep_weights(const float* __restrict__ w1, const float* __restrict__ w2)
{
    size_t idx = (size_t)blockIdx.x * blockDim.x + threadIdx.x;
    const size_t HALF = (size_t)2 * 64 * 64 * 128;   // 1,048,576
    if (idx < HALF) {
        int e = idx & 127, d = (idx >> 7) & 63;
        size_t t = idx >> 13;
        g_w1t[t * 8192 + e * 64 + d] = __float2half_rn(w1[idx]);
    } else if (idx < 2 * HALF) {
        size_t i2 = idx - HALF;
        int o = i2 & 63, e = (i2 >> 6) & 127;
        size_t t = i2 >> 13;
        g_w2t[t * 8192 + o * 128 + e] = __float2half_rn(w2[i2]);
    }
}

// ============== fused block MLP: fp16 HMMA single-pass, 4 CTAs/SM ==============
__global__ __launch_bounds__(512, 4)
void mlp_tc_kernel(const float* __restrict__ act_in, float* __restrict__ act_out,
                   int layer, const float* __restrict__ b1g, const float* __restrict__ b2g)
{
    extern __shared__ unsigned char smem[];
    float* b1s = (float*)(smem + SB_B1);
    float* b2s = (float*)(smem + SB_B2);
    float* Os  = (float*)(smem + SB_OUT);
    const uint32_t sb = smem_u32(smem);

    const int tid = threadIdx.x;
    const int m = blockIdx.x, n = blockIdx.y;
    const size_t t = (size_t)layer * 64 + n;
    const size_t row0 = (size_t)m * 128;

    // ---- load A tile + convert to fp16 inline ----
    {
        const float* src = act_in + row0 * DIM + (size_t)n * BLK;
        for (int idx = tid; idx < 2048; idx += 512) {
            int rr = idx >> 4, c4 = idx & 15;
            float4 v = *reinterpret_cast<const float4*>(src + (size_t)rr * DIM + c4 * 4);
            uint2 h;
            h.x = pack_h2(v.x, v.y);
            h.y = pack_h2(v.z, v.w);
            uint32_t off = (uint32_t)(rr * LDA + c4 * 4) * 2;
            *(uint2*)(smem + SB_A + off) = h;
        }
    }
    // ---- copy weights into padded smem tiles ----
    {
        const uint32_t* s1 = (const uint32_t*)(g_w1t + t * 8192);
        const uint32_t* s2 = (const uint32_t*)(g_w2t + t * 8192);
        for (int i = tid; i < 4096; i += 512) {
            int e = i >> 5, p = i & 31;
            uint32_t doff = (uint32_t)(e * LDA + p * 2) * 2;
            *(uint32_t*)(smem + SB_W1 + doff) = s1[i];
            int o = i >> 6, q = i & 63;
            uint32_t doff2 = (uint32_t)(o * LDH + q * 2) * 2;
            *(uint32_t*)(smem + SB_W2 + doff2) = s2[i];
        }
        if (tid < 128)      b1s[tid] = b1g[(size_t)n * HID + tid];
        else if (tid < 192) b2s[tid - 128] = b2g[(size_t)n * BLK + (tid - 128)];
    }
    __syncthreads();

    const int w = tid >> 5, lane = tid & 31;
    const int stripe = w >> 1, nh = w & 1;           // 8 row-stripes x 2 N-halves
    const int g = lane >> 2, tg = lane & 3;
    const int row = stripe * 16 + g;

    // ldmatrix address pieces
    const uint32_t arow = (uint32_t)(stripe * 16 + (lane & 15));
    const uint32_t akh  = (uint32_t)((lane >> 4) << 4);           // 0/16 bytes
    const uint32_t baseA = sb + SB_A + arow * (LDA * 2) + akh;
    const uint32_t bmi  = (uint32_t)(lane >> 3);
    const uint32_t bkh  = (bmi & 1) << 4;
    const uint32_t brow = (uint32_t)(((bmi >> 1) << 3) + (lane & 7));
    const uint32_t baseW1 = sb + SB_W1 + ((uint32_t)nh * 64 + brow) * (LDA * 2) + bkh;

    // ================= GEMM1: H(128x128) = A @ W1^T  (fp16) =================
    float acc[8][4];
#pragma unroll
    for (int i = 0; i < 8; i++) { acc[i][0] = acc[i][1] = acc[i][2] = acc[i][3] = 0.f; }

#pragma unroll
    for (int kt = 0; kt < 4; kt++) {
        const uint32_t ko = (uint32_t)kt * 32;
        uint32_t a0, a1, a2, a3;
        ldsm4(a0, a1, a2, a3, baseA + ko);
#pragma unroll
        for (int p = 0; p < 4; p++) {                 // nt pair (2p, 2p+1)
            uint32_t b0a, b1a, b0b, b1b;
            ldsm4(b0a, b1a, b0b, b1b, baseW1 + (uint32_t)p * (16 * LDA * 2) + ko);
            mma16816(acc[2 * p],     a0, a1, a2, a3, b0a, b1a);
            mma16816(acc[2 * p + 1], a0, a1, a2, a3, b0b, b1b);
        }
    }
    __syncthreads();   // GEMM1 smem reads done before H overlays A/W1

    // ---- epilogue 1: bias + ELU -> H fp16 tile ----
#pragma unroll
    for (int nt = 0; nt < 8; nt++) {
        int c0 = nh * 64 + nt * 8 + 2 * tg;
        float bb0 = b1s[c0], bb1 = b1s[c0 + 1];
        float v0 = elu1(acc[nt][0] + bb0);
        float v1 = elu1(acc[nt][1] + bb1);
        float v2 = elu1(acc[nt][2] + bb0);
        float v3 = elu1(acc[nt][3] + bb1);
        uint32_t o0 = (uint32_t)(row * LDH + c0) * 2;
        uint32_t o1 = (uint32_t)((row + 8) * LDH + c0) * 2;
        *(uint32_t*)(smem + SB_H + o0) = pack_h2(v0, v1);
        *(uint32_t*)(smem + SB_H + o1) = pack_h2(v2, v3);
    }
    __syncthreads();

    // ================= GEMM2: O(128x64) = H @ W2^T  (fp16) =================
    float acc2[4][4];
#pragma unroll
    for (int i = 0; i < 4; i++) { acc2[i][0] = acc2[i][1] = acc2[i][2] = acc2[i][3] = 0.f; }

    const uint32_t baseH  = sb + SB_H + arow * (LDH * 2) + akh;
    const uint32_t brow2  = (uint32_t)(nh * 32 + ((bmi >> 1) << 3) + (lane & 7));
    const uint32_t baseW2 = sb + SB_W2 + brow2 * (LDH * 2) + bkh;

#pragma unroll
    for (int kt = 0; kt < 8; kt++) {
        const uint32_t ko = (uint32_t)kt * 32;
        uint32_t a0, a1, a2, a3;
        ldsm4(a0, a1, a2, a3, baseH + ko);
#pragma unroll
        for (int p = 0; p < 2; p++) {                 // nt pair (2p, 2p+1)
            uint32_t b0a, b1a, b0b, b1b;
            ldsm4(b0a, b1a, b0b, b1b, baseW2 + (uint32_t)p * (16 * LDH * 2) + ko);
            mma16816(acc2[2 * p],     a0, a1, a2, a3, b0a, b1a);
            mma16816(acc2[2 * p + 1], a0, a1, a2, a3, b0b, b1b);
        }
    }
    __syncthreads();   // all GEMM2 H reads done before OUT overlays H

    // ---- epilogue 2: acc2 + b2 -> OUT smem ----
#pragma unroll
    for (int nt = 0; nt < 4; nt++) {
        int c0 = nh * 32 + nt * 8 + 2 * tg;
        float bb0 = b2s[c0], bb1 = b2s[c0 + 1];
        Os[row * 68 + c0]           = acc2[nt][0] + bb0;
        Os[row * 68 + c0 + 1]       = acc2[nt][1] + bb1;
        Os[(row + 8) * 68 + c0]     = acc2[nt][2] + bb0;
        Os[(row + 8) * 68 + c0 + 1] = acc2[nt][3] + bb1;
    }
    __syncthreads();

    // ---- store: OUT + residual (re-read from gmem, coalesced) ----
    {
        const float* rsrc = act_in + row0 * DIM + (size_t)n * BLK;
        float* dst = act_out + row0 * DIM + (size_t)n * BLK;
        for (int idx = tid; idx < 2048; idx += 512) {
            int rr = idx >> 4, c4 = idx & 15;
            float4 o = *reinterpret_cast<const float4*>(&Os[rr * 68 + c4 * 4]);
            float4 a = *reinterpret_cast<const float4*>(rsrc + (size_t)rr * DIM + c4 * 4);
            o.x += a.x; o.y += a.y; o.z += a.z; o.w += a.w;
            *reinterpret_cast<float4*>(dst + (size_t)rr * DIM + c4 * 4) = o;
        }
    }
}

// ============== per-row 64x64 transpose, 2 rows/CTA, float4 both sides ==============
__global__ __launch_bounds__(256)
void transpose64_kernel(const float* __restrict__ in, float* __restrict__ out)
{
    __shared__ float s[2][64 * 65];
    const size_t base = (size_t)blockIdx.x * 2 * DIM;
    const int tid = threadIdx.x;
    for (int i = tid; i < 2048; i += 256) {
        int r = i >> 10, j = i & 1023;
        int a = j >> 4, q = j & 15;
        float4 v = *reinterpret_cast<const float4*>(in + base + (size_t)r * DIM + a * 64 + q * 4);
        float* sp = &s[r][a * 65 + q * 4];
        sp[0] = v.x; sp[1] = v.y; sp[2] = v.z; sp[3] = v.w;
    }
    __syncthreads();
    for (int i = tid; i < 2048; i += 256) {
        int r = i >> 10, j = i & 1023;
        int b = j >> 4, q = j & 15;
        float4 v;
        v.x = s[r][(q * 4 + 0) * 65 + b];
        v.y = s[r][(q * 4 + 1) * 65 + b];
        v.z = s[r][(q * 4 + 2) * 65 + b];
        v.w = s[r][(q * 4 + 3) * 65 + b];
        *reinterpret_cast<float4*>(out + base + (size_t)r * DIM + b * 64 + q * 4) = v;
    }
}

static float* symbol_addr(const void* sym)
{
    void* p = nullptr;
    cudaGetSymbolAddress(&p, sym);
    return (float*)p;
}

extern "C" void kernel_launch(void* const* d_in, const int* in_sizes, int n_in,
                              void* d_out, int out_size)
{
    (void)in_sizes; (void)n_in; (void)out_size;
    const float* x  = (const float*)d_in[0];
    const float* w1 = (const float*)d_in[1];
    const float* b1 = (const float*)d_in[2];
    const float* w2 = (const float*)d_in[3];
    const float* b2 = (const float*)d_in[4];
    float* out = (float*)d_out;

    float* bufA = symbol_addr(g_bufA);
    float* bufB = symbol_addr(g_bufB);

    cudaFuncSetAttribute((const void*)mlp_tc_kernel,
                         cudaFuncAttributeMaxDynamicSharedMemorySize, SMEM_TOTAL);

    prep_weights<<<4096, 512>>>(w1, w2);

    const dim3 grid(BS / 128, NB);
    const size_t ob1 = (size_t)NB * HID, ob2 = (size_t)NB * BLK;

    // layer 0 (gap=1 shuffle = identity)
    mlp_tc_kernel<<<grid, 512, SMEM_TOTAL>>>(x, bufA, 0, b1, b2);
    // gap=64 shuffle: per-row 64x64 transpose
    transpose64_kernel<<<BS / 2, 256>>>(bufA, bufB);
    // layer 1
    mlp_tc_kernel<<<grid, 512, SMEM_TOTAL>>>(bufB, bufA, 1, b1 + ob1, b2 + ob2);
    // inverse shuffle
    transpose64_kernel<<<BS / 2, 256>>>(bufA, out);
}

// round 15
// speedup vs baseline: 1.7701x; 1.7701x over previous
#include <cuda_runtime.h>
#include <cuda_fp16.h>
#include <cstdint>

#define BS   8192
#define DIM  4096
#define BLK  64
#define NB   64
#define HID  128

// ================= device scratch (no allocs allowed) =================
__device__ float g_bufA[(size_t)BS * DIM];
__device__ float g_bufB[(size_t)BS * DIM];
// prepped fp16 weights, dense k-contiguous:
//   W1^T: [t][e=128][d=64]   W2^T: [t][o=64][e=128]     (t = layer*64 + n)
__device__ __half g_w1t[2 * 64 * 8192];
__device__ __half g_w2t[2 * 64 * 8192];

// ================= smem layout (bytes) =================
// Phase 1 (GEMM1):  A fp16 [0,18432)  W1 fp16 [18432,36864)
// Phase 2 (GEMM2):  H fp16 [0,34816)   (overlays A+W1)
// Phase 3 (store):  OUT f32 [0,34816)  (overlays H)
// Always:           W2 fp16 [36864,54272)  b1/b2 [54272,55040)
#define SB_A      0
#define SB_W1     18432
#define SB_H      0
#define SB_OUT    0
#define SB_W2     36864
#define SB_B1     54272
#define SB_B2     54784
#define SMEM_TOTAL 55040

#define LDA 72    // fp16 stride, A / W1^T  (144 B/row: LDSM conflict-free)
#define LDH 136   // fp16 stride, H / W2^T  (272 B/row: LDSM conflict-free)

__device__ __forceinline__ uint32_t smem_u32(const void* p) {
    uint32_t a;
    asm("{ .reg .u64 t; cvta.to.shared.u64 t, %1; cvt.u32.u64 %0, t; }" : "=r"(a) : "l"(p));
    return a;
}

__device__ __forceinline__ uint32_t pack_h2(float a, float b) {
    __half2 h = __floats2half2_rn(a, b);
    return *reinterpret_cast<uint32_t*>(&h);
}

// D = A(16x16,row) * B(16x8,col) + D ; fp16 in, f32 accum
__device__ __forceinline__ void mma16816(float* c, uint32_t a0, uint32_t a1,
                                         uint32_t a2, uint32_t a3,
                                         uint32_t b0, uint32_t b1) {
    asm("mma.sync.aligned.m16n8k16.row.col.f32.f16.f16.f32 "
        "{%0,%1,%2,%3}, {%4,%5,%6,%7}, {%8,%9}, {%0,%1,%2,%3};"
        : "+f"(c[0]), "+f"(c[1]), "+f"(c[2]), "+f"(c[3])
        : "r"(a0), "r"(a1), "r"(a2), "r"(a3), "r"(b0), "r"(b1));
}

__device__ __forceinline__ void ldsm4(uint32_t& r0, uint32_t& r1, uint32_t& r2,
                                      uint32_t& r3, uint32_t addr) {
    asm volatile("ldmatrix.sync.aligned.m8n8.x4.shared.b16 {%0,%1,%2,%3}, [%4];"
                 : "=r"(r0), "=r"(r1), "=r"(r2), "=r"(r3) : "r"(addr));
}

__device__ __forceinline__ float elu1(float v) {
    return (v > 0.f) ? v : (__expf(v) - 1.f);
}

// ============== weight prep: fp32 -> transposed fp16 ==============
__global__ void prep_weights(const float* __restrict__ w1, const float* __restrict__ w2)
{
    size_t idx = (size_t)blockIdx.x * blockDim.x + threadIdx.x;
    const size_t HALF = (size_t)2 * 64 * 64 * 128;   // 1,048,576
    if (idx < HALF) {
        int e = idx & 127, d = (idx >> 7) & 63;
        size_t t = idx >> 13;
        g_w1t[t * 8192 + e * 64 + d] = __float2half_rn(w1[idx]);
    } else if (idx < 2 * HALF) {
        size_t i2 = idx - HALF;
        int o = i2 & 63, e = (i2 >> 6) & 127;
        size_t t = i2 >> 13;
        g_w2t[t * 8192 + o * 128 + e] = __float2half_rn(w2[i2]);
    }
}

// ============== fused block MLP: fp16 HMMA single-pass, 2 CTAs/SM ==============
__global__ __launch_bounds__(512, 2)
void mlp_tc_kernel(const float* __restrict__ act_in, float* __restrict__ act_out,
                   int layer, const float* __restrict__ b1g, const float* __restrict__ b2g)
{
    extern __shared__ unsigned char smem[];
    float* b1s = (float*)(smem + SB_B1);
    float* b2s = (float*)(smem + SB_B2);
    float* Os  = (float*)(smem + SB_OUT);
    const uint32_t sb = smem_u32(smem);

    const int tid = threadIdx.x;
    const int m = blockIdx.x, n = blockIdx.y;
    const size_t t = (size_t)layer * 64 + n;
    const size_t row0 = (size_t)m * 128;

    // ---- load A tile + convert to fp16 inline ----
    {
        const float* src = act_in + row0 * DIM + (size_t)n * BLK;
        for (int idx = tid; idx < 2048; idx += 512) {
            int rr = idx >> 4, c4 = idx & 15;
            float4 v = *reinterpret_cast<const float4*>(src + (size_t)rr * DIM + c4 * 4);
            uint2 h;
            h.x = pack_h2(v.x, v.y);
            h.y = pack_h2(v.z, v.w);
            uint32_t off = (uint32_t)(rr * LDA + c4 * 4) * 2;
            *(uint2*)(smem + SB_A + off) = h;
        }
    }
    // ---- copy weights into padded smem tiles ----
    {
        const uint32_t* s1 = (const uint32_t*)(g_w1t + t * 8192);
        const uint32_t* s2 = (const uint32_t*)(g_w2t + t * 8192);
        for (int i = tid; i < 4096; i += 512) {
            int e = i >> 5, p = i & 31;
            uint32_t doff = (uint32_t)(e * LDA + p * 2) * 2;
            *(uint32_t*)(smem + SB_W1 + doff) = s1[i];
            int o = i >> 6, q = i & 63;
            uint32_t doff2 = (uint32_t)(o * LDH + q * 2) * 2;
            *(uint32_t*)(smem + SB_W2 + doff2) = s2[i];
        }
        if (tid < 128)      b1s[tid] = b1g[(size_t)n * HID + tid];
        else if (tid < 192) b2s[tid - 128] = b2g[(size_t)n * BLK + (tid - 128)];
    }
    __syncthreads();

    const int w = tid >> 5, lane = tid & 31;
    const int stripe = w >> 1, nh = w & 1;           // 8 row-stripes x 2 N-halves
    const int g = lane >> 2, tg = lane & 3;
    const int row = stripe * 16 + g;

    // ldmatrix address pieces
    const uint32_t arow = (uint32_t)(stripe * 16 + (lane & 15));
    const uint32_t akh  = (uint32_t)((lane >> 4) << 4);           // 0/16 bytes
    const uint32_t baseA = sb + SB_A + arow * (LDA * 2) + akh;
    const uint32_t bmi  = (uint32_t)(lane >> 3);
    const uint32_t bkh  = (bmi & 1) << 4;
    const uint32_t brow = (uint32_t)(((bmi >> 1) << 3) + (lane & 7));
    const uint32_t baseW1 = sb + SB_W1 + ((uint32_t)nh * 64 + brow) * (LDA * 2) + bkh;

    // ================= GEMM1: H(128x128) = A @ W1^T  (fp16) =================
    float acc[8][4];
#pragma unroll
    for (int i = 0; i < 8; i++) { acc[i][0] = acc[i][1] = acc[i][2] = acc[i][3] = 0.f; }

#pragma unroll
    for (int kt = 0; kt < 4; kt++) {
        const uint32_t ko = (uint32_t)kt * 32;
        uint32_t a0, a1, a2, a3;
        ldsm4(a0, a1, a2, a3, baseA + ko);
#pragma unroll
        for (int p = 0; p < 4; p++) {                 // nt pair (2p, 2p+1)
            uint32_t b0a, b1a, b0b, b1b;
            ldsm4(b0a, b1a, b0b, b1b, baseW1 + (uint32_t)p * (16 * LDA * 2) + ko);
            mma16816(acc[2 * p],     a0, a1, a2, a3, b0a, b1a);
            mma16816(acc[2 * p + 1], a0, a1, a2, a3, b0b, b1b);
        }
    }
    __syncthreads();   // GEMM1 smem reads done before H overlays A/W1

    // ---- epilogue 1: bias + ELU -> H fp16 tile ----
#pragma unroll
    for (int nt = 0; nt < 8; nt++) {
        int c0 = nh * 64 + nt * 8 + 2 * tg;
        float bb0 = b1s[c0], bb1 = b1s[c0 + 1];
        float v0 = elu1(acc[nt][0] + bb0);
        float v1 = elu1(acc[nt][1] + bb1);
        float v2 = elu1(acc[nt][2] + bb0);
        float v3 = elu1(acc[nt][3] + bb1);
        uint32_t o0 = (uint32_t)(row * LDH + c0) * 2;
        uint32_t o1 = (uint32_t)((row + 8) * LDH + c0) * 2;
        *(uint32_t*)(smem + SB_H + o0) = pack_h2(v0, v1);
        *(uint32_t*)(smem + SB_H + o1) = pack_h2(v2, v3);
    }
    __syncthreads();

    // ================= GEMM2: O(128x64) = H @ W2^T  (fp16) =================
    float acc2[4][4];
#pragma unroll
    for (int i = 0; i < 4; i++) { acc2[i][0] = acc2[i][1] = acc2[i][2] = acc2[i][3] = 0.f; }

    const uint32_t baseH  = sb + SB_H + arow * (LDH * 2) + akh;
    const uint32_t brow2  = (uint32_t)(nh * 32 + ((bmi >> 1) << 3) + (lane & 7));
    const uint32_t baseW2 = sb + SB_W2 + brow2 * (LDH * 2) + bkh;

#pragma unroll
    for (int kt = 0; kt < 8; kt++) {
        const uint32_t ko = (uint32_t)kt * 32;
        uint32_t a0, a1, a2, a3;
        ldsm4(a0, a1, a2, a3, baseH + ko);
#pragma unroll
        for (int p = 0; p < 2; p++) {                 // nt pair (2p, 2p+1)
            uint32_t b0a, b1a, b0b, b1b;
            ldsm4(b0a, b1a, b0b, b1b, baseW2 + (uint32_t)p * (16 * LDH * 2) + ko);
            mma16816(acc2[2 * p],     a0, a1, a2, a3, b0a, b1a);
            mma16816(acc2[2 * p + 1], a0, a1, a2, a3, b0b, b1b);
        }
    }
    __syncthreads();   // all GEMM2 H reads done before OUT overlays H

    // ---- epilogue 2: acc2 + b2 -> OUT smem ----
#pragma unroll
    for (int nt = 0; nt < 4; nt++) {
        int c0 = nh * 32 + nt * 8 + 2 * tg;
        float bb0 = b2s[c0], bb1 = b2s[c0 + 1];
        Os[row * 68 + c0]           = acc2[nt][0] + bb0;
        Os[row * 68 + c0 + 1]       = acc2[nt][1] + bb1;
        Os[(row + 8) * 68 + c0]     = acc2[nt][2] + bb0;
        Os[(row + 8) * 68 + c0 + 1] = acc2[nt][3] + bb1;
    }
    __syncthreads();

    // ---- store: OUT + residual (re-read from gmem, coalesced) ----
    {
        const float* rsrc = act_in + row0 * DIM + (size_t)n * BLK;
        float* dst = act_out + row0 * DIM + (size_t)n * BLK;
        for (int idx = tid; idx < 2048; idx += 512) {
            int rr = idx >> 4, c4 = idx & 15;
            float4 o = *reinterpret_cast<const float4*>(&Os[rr * 68 + c4 * 4]);
            float4 a = *reinterpret_cast<const float4*>(rsrc + (size_t)rr * DIM + c4 * 4);
            o.x += a.x; o.y += a.y; o.z += a.z; o.w += a.w;
            *reinterpret_cast<float4*>(dst + (size_t)rr * DIM + c4 * 4) = o;
        }
    }
}

// ============== per-row 64x64 transpose, 2 rows/CTA, float4 both sides ==============
__global__ __launch_bounds__(256)
void transpose64_kernel(const float* __restrict__ in, float* __restrict__ out)
{
    __shared__ float s[2][64 * 65];
    const size_t base = (size_t)blockIdx.x * 2 * DIM;
    const int tid = threadIdx.x;
    for (int i = tid; i < 2048; i += 256) {
        int r = i >> 10, j = i & 1023;
        int a = j >> 4, q = j & 15;
        float4 v = *reinterpret_cast<const float4*>(in + base + (size_t)r * DIM + a * 64 + q * 4);
        float* sp = &s[r][a * 65 + q * 4];
        sp[0] = v.x; sp[1] = v.y; sp[2] = v.z; sp[3] = v.w;
    }
    __syncthreads();
    for (int i = tid; i < 2048; i += 256) {
        int r = i >> 10, j = i & 1023;
        int b = j >> 4, q = j & 15;
        float4 v;
        v.x = s[r][(q * 4 + 0) * 65 + b];
        v.y = s[r][(q * 4 + 1) * 65 + b];
        v.z = s[r][(q * 4 + 2) * 65 + b];
        v.w = s[r][(q * 4 + 3) * 65 + b];
        *reinterpret_cast<float4*>(out + base + (size_t)r * DIM + b * 64 + q * 4) = v;
    }
}

static float* symbol_addr(const void* sym)
{
    void* p = nullptr;
    cudaGetSymbolAddress(&p, sym);
    return (float*)p;
}

extern "C" void kernel_launch(void* const* d_in, const int* in_sizes, int n_in,
                              void* d_out, int out_size)
{
    (void)in_sizes; (void)n_in; (void)out_size;
    const float* x  = (const float*)d_in[0];
    const float* w1 = (const float*)d_in[1];
    const float* b1 = (const float*)d_in[2];
    const float* w2 = (const float*)d_in[3];
    const float* b2 = (const float*)d_in[4];
    float* out = (float*)d_out;

    float* bufA = symbol_addr(g_bufA);
    float* bufB = symbol_addr(g_bufB);

    cudaFuncSetAttribute((const void*)mlp_tc_kernel,
                         cudaFuncAttributeMaxDynamicSharedMemorySize, SMEM_TOTAL);

    prep_weights<<<4096, 512>>>(w1, w2);

    const dim3 grid(BS / 128, NB);
    const size_t ob1 = (size_t)NB * HID, ob2 = (size_t)NB * BLK;

    // layer 0 (gap=1 shuffle = identity)
    mlp_tc_kernel<<<grid, 512, SMEM_TOTAL>>>(x, bufA, 0, b1, b2);
    // gap=64 shuffle: per-row 64x64 transpose
    transpose64_kernel<<<BS / 2, 256>>>(bufA, bufB);
    // layer 1
    mlp_tc_kernel<<<grid, 512, SMEM_TOTAL>>>(bufB, bufA, 1, b1 + ob1, b2 + ob2);
    // inverse shuffle
    transpose64_kernel<<<BS / 2, 256>>>(bufA, out);
}